// round 1
// baseline (speedup 1.0000x reference)
#include <cuda_runtime.h>
#include <cuda_bf16.h>

// Gather: out[i, y, x, c] = logits[i * N_SP + segments[i, y, x], c]
// Shapes (fixed by the problem):
//   logits:   [N_IMG * N_SP, WAY] fp32   = [8192, 5]
//   segments: [N_IMG, SIZE, SIZE] int32  = [16, 512, 512], values in [0, N_SP)
//   out:      [N_IMG, SIZE, SIZE, WAY] fp32
//
// Strategy: one thread per output float4. Floats [4j, 4j+4) span at most two
// pixels; load their segment ids (coalesced, L2-cached), gather 4 logit floats
// (logits table is 10KB/image -> L1 resident), emit one coalesced STG.128.

#define N_IMG 16
#define SIZE  512
#define N_SP  512
#define WAY   5
#define PIX_PER_IMG (SIZE * SIZE)            // 262144 = 1 << 18
#define PIX_SHIFT   18
#define LOGITS_PER_IMG (N_SP * WAY)          // 2560

__global__ void __launch_bounds__(256)
sp_gather_kernel(const float* __restrict__ logits,
                 const int* __restrict__ seg,
                 float4* __restrict__ out,
                 int n_vec)
{
    int j = blockIdx.x * blockDim.x + threadIdx.x;
    if (j >= n_vec) return;

    int f0 = j << 2;                 // first output float index (fits in int31)

    // The 4 floats cover pixels p_a .. p_b where p_b <= p_a + 1.
    int p_a = f0 / 5;
    int p_b = (f0 + 3) / 5;
    int s_a = __ldg(seg + p_a);
    int s_b = __ldg(seg + p_b);      // may equal s_a; L2/L1 absorbs it

    float v[4];
#pragma unroll
    for (int k = 0; k < 4; ++k) {
        int f   = f0 + k;
        int p   = f / 5;             // pixel
        int c   = f - 5 * p;         // channel
        int img = p >> PIX_SHIFT;    // image id
        int s   = (p == p_a) ? s_a : s_b;
        v[k] = __ldg(logits + img * LOGITS_PER_IMG + s * WAY + c);
    }

    out[j] = make_float4(v[0], v[1], v[2], v[3]);
}

extern "C" void kernel_launch(void* const* d_in, const int* in_sizes, int n_in,
                              void* d_out, int out_size)
{
    const float* logits = (const float*)d_in[0];
    const int*   seg    = (const int*)d_in[1];
    float4*      out    = (float4*)d_out;

    int n_vec = out_size >> 2;       // out_size = 20,971,520, divisible by 4
    int threads = 256;
    int blocks = (n_vec + threads - 1) / threads;
    sp_gather_kernel<<<blocks, threads>>>(logits, seg, out, n_vec);
}

// round 2
// speedup vs baseline: 1.5373x; 1.5373x over previous
#include <cuda_runtime.h>
#include <cuda_bf16.h>

// Gather: out[i, y, x, c] = logits[i * N_SP + segments[i, y, x], c]
//   logits:   [16*512, 5] fp32 (10 KB per image)
//   segments: [16, 512, 512] int32
//   out:      [16, 512, 512, 5] fp32
//
// R2 strategy: stage the per-image 10KB logits table in SMEM; gather via LDS
// instead of scattered LDG (R1 showed L1tex wavefronts were the bottleneck at
// 53% with DRAM at only 14%). One thread per output float4, coalesced STG.128.
// 64 blocks x 1024 threads per image, 5 float4s per thread, so staging traffic
// is only 10 MB total.

#define N_IMG 16
#define SIZE  512
#define N_SP  512
#define WAY   5
#define PIX_PER_IMG   (SIZE * SIZE)          // 262144
#define FLOATS_PER_IMG (PIX_PER_IMG * WAY)   // 1310720
#define VEC_PER_IMG   (FLOATS_PER_IMG / 4)   // 327680
#define LOGITS_PER_IMG (N_SP * WAY)          // 2560 floats = 10 KB

#define THREADS 1024
#define BLOCKS_PER_IMG 64
#define ITERS (VEC_PER_IMG / (BLOCKS_PER_IMG * THREADS))  // 5
#define VEC_PER_BLOCK (THREADS * ITERS)                   // 5120

__global__ void __launch_bounds__(THREADS)
sp_gather_smem_kernel(const float* __restrict__ logits,
                      const int* __restrict__ seg,
                      float4* __restrict__ out)
{
    __shared__ float s_logits[LOGITS_PER_IMG];

    const int img = blockIdx.y;
    const int blk = blockIdx.x;           // 0..BLOCKS_PER_IMG-1
    const int tid = threadIdx.x;

    // Stage this image's logits table: 2560 floats = 640 float4s, coalesced.
    const float4* ltab = (const float4*)(logits + img * LOGITS_PER_IMG);
    float4* stab = (float4*)s_logits;
#pragma unroll
    for (int i = tid; i < LOGITS_PER_IMG / 4; i += THREADS)
        stab[i] = ltab[i];
    __syncthreads();

    const int* seg_img = seg + img * PIX_PER_IMG;
    float4* out_img = out + img * VEC_PER_IMG;
    const int base = blk * VEC_PER_BLOCK;

#pragma unroll
    for (int it = 0; it < ITERS; ++it) {
        int j = base + it * THREADS + tid;   // float4 index within image
        int f0 = j << 2;                     // float index within image

        // 4 floats span at most two pixels
        int p_a = f0 / 5;
        int p_b = (f0 + 3) / 5;
        int s_a = __ldg(seg_img + p_a);
        int s_b = __ldg(seg_img + p_b);

        float v[4];
#pragma unroll
        for (int k = 0; k < 4; ++k) {
            int f = f0 + k;
            int p = f / 5;
            int c = f - 5 * p;
            int s = (p == p_a) ? s_a : s_b;
            v[k] = s_logits[s * WAY + c];
        }
        out_img[j] = make_float4(v[0], v[1], v[2], v[3]);
    }
}

extern "C" void kernel_launch(void* const* d_in, const int* in_sizes, int n_in,
                              void* d_out, int out_size)
{
    const float* logits = (const float*)d_in[0];
    const int*   seg    = (const int*)d_in[1];
    float4*      out    = (float4*)d_out;

    dim3 grid(BLOCKS_PER_IMG, N_IMG);
    sp_gather_smem_kernel<<<grid, THREADS>>>(logits, seg, out);
}